// round 6
// baseline (speedup 1.0000x reference)
#include <cuda_runtime.h>
#include <math.h>

#define BATCH   32
#define H       384
#define KK      378
#define NS      7
#define NSHIFT  49
#define TILE    54
#define PATCH   60
#define NTOT_D  4572288.0

#define STATS_BLOCKS  1568          // 7*7*32
#define ROWS_TOTAL    (BATCH * H)   // 12288
#define ROW_BLOCKS    1756          // ceil(12288 / 7)
#define MAIN_BLOCKS   (STATS_BLOCKS + ROW_BLOCKS)
#define ZB            592           // zcorr blocks
#define ZGROUPS       (ZB * 4)      // 64-thread groups
#define ZW_BLOCKS     (ZB + 28)
#define MAE_BLOCKS    1512          // 12096 rows / 8 warps

typedef unsigned long long ull;

// ---------------- global scratch (no allocations allowed) ----------------
__device__ double g_tp[NSHIFT];            // dense cross: sum t*p per shift
__device__ double g_zp[NSHIFT];            // sparse cross: sum z*p per shift
__device__ double g_win[NSHIFT * 4];       // windowed sums: t, t^2, m, m*t
__device__ double g_sp[32];                // global sum p (spread slots)
__device__ double g_sp2[32];               // global sum p^2 (spread slots)
__device__ double g_abs[32];               // MAE accumulation (spread slots)
__device__ int    g_idx;
__device__ unsigned int g_zcount;
__device__ unsigned int g_done_zw;
__device__ unsigned int g_done_mae;
__device__ float  g_W[4 * NS * BATCH * H]; // per-row windowed sums [f][v][b][y]
__device__ int    g_zlist[BATCH * H * H];  // worst-case capacity

__device__ __forceinline__ void ffma2(ull& d, ull a, ull b) {
    asm("fma.rn.f32x2 %0, %1, %2, %0;" : "+l"(d) : "l"(a), "l"(b));
}
__device__ __forceinline__ ull pk2(float lo, float hi) {
    ull r;
    asm("mov.b64 %0, {%1, %2};" : "=l"(r) : "f"(lo), "f"(hi));
    return r;
}

__global__ void init_kernel() {
    int t = threadIdx.x;
    if (t < NSHIFT) { g_tp[t] = 0.0; g_zp[t] = 0.0; }
    if (t < 32) { g_sp[t] = 0.0; g_sp2[t] = 0.0; g_abs[t] = 0.0; }
    if (t == 0) { g_idx = 0; g_zcount = 0u; g_done_zw = 0u; g_done_mae = 0u; }
}

// ======== fused main kernel: stats blocks + rowsum blocks ========
__global__ __launch_bounds__(224) void main_kernel(
    const float* __restrict__ pred, const float* __restrict__ target)
{
    __shared__ float sT[PATCH * PATCH];
    __shared__ float sP[TILE * TILE];

    const int tid  = threadIdx.x;
    const int lane = tid & 31;
    const int wid  = tid >> 5;

    if (blockIdx.x < STATS_BLOCKS) {
        // ---- dense cross-correlation: sum t*p per shift via FFMA2 ----
        const int bid = blockIdx.x;
        const int tx = bid % 7;
        const int ty = (bid / 7) % 7;
        const int b  = bid / 49;
        const int x0 = tx * TILE;
        const int y0 = ty * TILE;
        const float* tb = target + (size_t)b * H * H;
        const float* pb = pred   + (size_t)b * H * H;

        for (int k = tid; k < PATCH * PATCH; k += 224) {
            int yy = k / PATCH, xx = k - yy * PATCH;
            sT[k] = tb[(y0 + yy) * H + (x0 + xx)];
        }
        for (int k = tid; k < TILE * TILE; k += 224) {
            int i = k / TILE, j = k - i * TILE;
            sP[k] = pb[(y0 + i + 3) * H + (x0 + j + 3)];
        }
        __syncthreads();

        ull acc2[NS];
#pragma unroll
        for (int v = 0; v < NS; v++) acc2[v] = 0ull;

        // 54 rows x 9 groups of 6 px = 486 groups; 486 = 32*15 + 6
#pragma unroll
        for (int it = 0; it < 16; it++) {
            int g = lane + 32 * it;
            if (it == 15 && lane >= 6) break;
            int i = g / 9;
            int j = (g - i * 9) * 6;
            const float2* trow = reinterpret_cast<const float2*>(&sT[(i + wid) * PATCH + j]);
            const float2* prow = reinterpret_cast<const float2*>(&sP[i * TILE + j]);
            float tt[12];
            ull   pp2[3];
#pragma unroll
            for (int k = 0; k < 6; k++) { float2 q = trow[k]; tt[2*k] = q.x; tt[2*k+1] = q.y; }
#pragma unroll
            for (int k = 0; k < 3; k++) { float2 q = prow[k]; pp2[k] = pk2(q.x, q.y); }
            ull q[11];
#pragma unroll
            for (int k = 0; k < 11; k++) q[k] = pk2(tt[k], tt[k + 1]);
#pragma unroll
            for (int e = 0; e < 3; e++) {
#pragma unroll
                for (int v = 0; v < NS; v++)
                    ffma2(acc2[v], q[2 * e + v], pp2[e]);
            }
        }

#pragma unroll
        for (int v = 0; v < NS; v++) {
            float tp = __uint_as_float((unsigned)acc2[v]) +
                       __uint_as_float((unsigned)(acc2[v] >> 32));
            for (int o = 16; o; o >>= 1)
                tp += __shfl_xor_sync(0xffffffffu, tp, o);
            if (lane == 0)
                atomicAdd(&g_tp[wid * NS + v], (double)tp);
        }
    } else {
        // ---- per-row windowed sums + pred sums + z compaction ----
        const int gw = (blockIdx.x - STATS_BLOCKS) * 7 + wid;
        if (gw >= ROWS_TOTAL) return;
        const int b = gw / H;
        const int y = gw - b * H;
        const float* row = target + ((size_t)b * H + y) * H;

        float s0 = 0.f, s1 = 0.f, s2 = 0.f, s3 = 0.f;
        unsigned zm = 0u;
#pragma unroll
        for (int k = 0; k < 12; k++) {
            int x = lane + 32 * k;
            float t = row[x];
            float m = (t > 5.f) ? 1.f : 0.f;
            s0 += t;
            s1  = fmaf(t, t, s1);
            s2 += m;
            s3  = fmaf(m, t, s3);
            if (t <= 5.f) zm |= (1u << k);
        }

        // compact z pixels: one atomic per row
        {
            unsigned cnt = (unsigned)__popc(zm);
            unsigned pre = cnt;
            for (int o = 1; o < 32; o <<= 1) {
                unsigned n = __shfl_up_sync(0xffffffffu, pre, o);
                if (lane >= o) pre += n;
            }
            unsigned tot  = __shfl_sync(0xffffffffu, pre, 31);
            unsigned excl = pre - cnt;
            unsigned base = 0;
            if (tot) {
                if (lane == 31) base = atomicAdd(&g_zcount, tot);
                base = __shfl_sync(0xffffffffu, base, 31);
                unsigned idx = base + excl;
                unsigned mm = zm;
                while (mm) {
                    int k = __ffs(mm) - 1;
                    mm &= mm - 1;
                    g_zlist[idx++] = (b * H + y) * H + lane + 32 * k;
                }
            }
        }

        for (int o = 16; o; o >>= 1) {
            s0 += __shfl_xor_sync(0xffffffffu, s0, o);
            s1 += __shfl_xor_sync(0xffffffffu, s1, o);
            s2 += __shfl_xor_sync(0xffffffffu, s2, o);
            s3 += __shfl_xor_sync(0xffffffffu, s3, o);
        }

        if (lane == 0) {
            float e[12];
#pragma unroll
            for (int k = 0; k < 6; k++) { e[k] = row[k]; e[6 + k] = row[378 + k]; }
#pragma unroll
            for (int v = 0; v < NS; v++) {
                float L0 = 0.f, L1 = 0.f, L2 = 0.f, L3 = 0.f;
                for (int x = 0; x < v; x++) {
                    float t = e[x];
                    float m = (t > 5.f) ? 1.f : 0.f;
                    L0 += t; L1 += t * t; L2 += m; L3 += m * t;
                }
                float R0 = 0.f, R1 = 0.f, R2 = 0.f, R3 = 0.f;
                for (int k = v; k < 6; k++) {
                    float t = e[6 + k];
                    float m = (t > 5.f) ? 1.f : 0.f;
                    R0 += t; R1 += t * t; R2 += m; R3 += m * t;
                }
                g_W[((0 * NS + v) * BATCH + b) * H + y] = s0 - L0 - R0;
                g_W[((1 * NS + v) * BATCH + b) * H + y] = s1 - L1 - R1;
                g_W[((2 * NS + v) * BATCH + b) * H + y] = s2 - L2 - R2;
                g_W[((3 * NS + v) * BATCH + b) * H + y] = s3 - L3 - R3;
            }
        }

        if (y >= 3 && y < 381) {
            const float* prow = pred + ((size_t)b * H + y) * H;
            float sp = 0.f, sp2 = 0.f;
#pragma unroll
            for (int k = 0; k < 12; k++) {
                int x = 3 + lane + 32 * k;
                if (x < 381) {
                    float p = prow[x];
                    sp += p;
                    sp2 = fmaf(p, p, sp2);
                }
            }
            for (int o = 16; o; o >>= 1) {
                sp  += __shfl_xor_sync(0xffffffffu, sp,  o);
                sp2 += __shfl_xor_sync(0xffffffffu, sp2, o);
            }
            if (lane == 0) {
                atomicAdd(&g_sp [gw & 31], (double)sp);
                atomicAdd(&g_sp2[gw & 31], (double)sp2);
            }
        }
    }
}

// ======== fused: zcorr blocks + winsum blocks + last-block argmin ========
__global__ __launch_bounds__(256) void zw_kernel(const float* __restrict__ pred,
                                                 float* out)
{
    __shared__ float  sAcc[64];
    __shared__ double col[H];
    __shared__ double red[256];
    __shared__ double scmse[64];
    __shared__ int    sidx[64];
    __shared__ int    sLast;

    const int tid = threadIdx.x;

    if (blockIdx.x < ZB) {
        // ---- sparse correction: shift-per-thread, scalar accumulator ----
        if (tid < 64) sAcc[tid] = 0.f;
        __syncthreads();

        const int sid = tid & 63;
        const int u = sid / NS, v = sid - (sid / NS) * NS;
        const bool active = sid < NSHIFT;
        const int grp = (blockIdx.x * 256 + tid) >> 6;
        const int count = (int)g_zcount;

        float acc = 0.f;
        for (int zi = grp; zi < count; zi += ZGROUPS) {
            int code = g_zlist[zi];
            int b = code / (H * H);
            int r = code - b * (H * H);
            int y = r / H;
            int x = r - y * H;
            if (active) {
                int yy = y - u;
                int xx = x - v;
                if (yy >= 0 && yy < KK && xx >= 0 && xx < KK)
                    acc += pred[(size_t)b * H * H + (yy + 3) * H + (xx + 3)];
            }
        }
        if (active && acc != 0.f) atomicAdd(&sAcc[sid], acc);
        __syncthreads();
        if (tid < NSHIFT && sAcc[tid] != 0.f)
            atomicAdd(&g_zp[tid], (double)sAcc[tid]);
    } else {
        // ---- combine per-row windowed sums: block per (f, v) ----
        const int wb = blockIdx.x - ZB;
        const int f = wb / NS;
        const int v = wb - f * NS;
        const float* Wfv = &g_W[((f * NS + v) * BATCH) * H];

        for (int y = tid; y < H; y += 256) {
            double s = 0.0;
#pragma unroll 4
            for (int b = 0; b < BATCH; b++)
                s += (double)Wfv[b * H + y];
            col[y] = s;
        }
        __syncthreads();

        double s = col[tid];
        if (tid + 256 < H) s += col[tid + 256];
        red[tid] = s;
        __syncthreads();
        for (int o = 128; o; o >>= 1) {
            if (tid < o) red[tid] += red[tid + o];
            __syncthreads();
        }
        if (tid < NS) {
            double T = red[0];
            for (int y = 0; y < tid; y++) T -= col[y];
            for (int y = tid + KK; y < H; y++) T -= col[y];
            g_win[(tid * NS + v) * 4 + f] = T;
        }
    }

    // ---- last block performs argmin + cPSNR ----
    __threadfence();
    __syncthreads();
    if (tid == 0)
        sLast = (atomicAdd(&g_done_zw, 1u) == (unsigned)(gridDim.x - 1));
    __syncthreads();
    if (!sLast) return;

    volatile double* vtp  = g_tp;
    volatile double* vzp  = g_zp;
    volatile double* vwin = g_win;
    volatile double* vsp  = g_sp;
    volatile double* vsp2 = g_sp2;

    double Sp = 0.0, Sp2 = 0.0;
    for (int k = 0; k < 32; k++) { Sp += vsp[k]; Sp2 += vsp2[k]; }

    if (tid < 64) {
        double c = 1e300;
        if (tid < NSHIFT) {
            double wt  = vwin[tid * 4 + 0];
            double wt2 = vwin[tid * 4 + 1];
            double n   = vwin[tid * 4 + 2];
            double wmt = vwin[tid * 4 + 3];
            double Sd  = wt - Sp;
            double Sd2 = wt2 - 2.0 * vtp[tid] + Sp2;
            double Sm  = wmt - (Sp - vzp[tid]);
            double bb  = Sm / n;
            c = (Sd2 - 2.0 * bb * Sd + NTOT_D * bb * bb) / n;
        }
        scmse[tid] = c; sidx[tid] = tid;
    }
    __syncthreads();
    for (int o = 32; o; o >>= 1) {
        if (tid < o) {
            if (scmse[tid + o] < scmse[tid]) {
                scmse[tid] = scmse[tid + o];
                sidx[tid]  = sidx[tid + o];
            }
        }
        __syncthreads();
    }
    if (tid == 0) {
        g_idx  = sidx[0];
        out[0] = (float)(-10.0 * log10(scmse[0]));
    }
}

// ======== MAE over winning shift + last-block finalize ========
__global__ __launch_bounds__(256) void mae_kernel(
    const float* __restrict__ pred, const float* __restrict__ target, float* out)
{
    const int idx = g_idx;
    const int u = idx / NS, v = idx - (idx / NS) * NS;
    const int gw   = blockIdx.x * 8 + (threadIdx.x >> 5);   // 0 .. 12095
    const int lane = threadIdx.x & 31;
    const int b    = gw / KK;
    const int i    = gw - b * KK;

    const float* prow = pred   + ((size_t)b * H + i + 3) * H + 3;
    const float* trow = target + ((size_t)b * H + i + u) * H + v;

    // fully unrolled: 378 = 32*11 + 26; two accumulators for ILP
    float a0 = 0.f, a1 = 0.f;
#pragma unroll
    for (int k = 0; k < 11; k++) {
        int x = lane + 32 * k;
        float d = fabsf(trow[x] - prow[x]);
        if (k & 1) a1 += d; else a0 += d;
    }
    if (lane < 26) {
        int x = lane + 352;
        a1 += fabsf(trow[x] - prow[x]);
    }
    float acc = a0 + a1;
    for (int o = 16; o; o >>= 1) acc += __shfl_xor_sync(0xffffffffu, acc, o);

    __shared__ float ssum[8];
    __shared__ int   sLast;
    const int w = threadIdx.x >> 5;
    if (lane == 0) ssum[w] = acc;
    __syncthreads();
    if (threadIdx.x == 0) {
        float a = 0.f;
#pragma unroll
        for (int k = 0; k < 8; k++) a += ssum[k];
        atomicAdd(&g_abs[blockIdx.x & 31], (double)a);
        __threadfence();
        sLast = (atomicAdd(&g_done_mae, 1u) == (unsigned)(gridDim.x - 1));
        if (sLast) {
            volatile double* ga = g_abs;
            double s = 0.0;
            for (int k = 0; k < 32; k++) s += ga[k];
            out[1] = (float)(s / NTOT_D);
        }
    }
}

extern "C" void kernel_launch(void* const* d_in, const int* in_sizes, int n_in,
                              void* d_out, int out_size) {
    const float* pred   = (const float*)d_in[0];
    const float* target = (const float*)d_in[1];
    float* out = (float*)d_out;

    init_kernel<<<1, 64>>>();
    main_kernel<<<MAIN_BLOCKS, 224>>>(pred, target);
    zw_kernel<<<ZW_BLOCKS, 256>>>(pred, out);
    mae_kernel<<<MAE_BLOCKS, 256>>>(pred, target, out);
}

// round 7
// speedup vs baseline: 1.0574x; 1.0574x over previous
#include <cuda_runtime.h>
#include <math.h>

#define BATCH   32
#define H       384
#define KK      378
#define NS      7
#define NSHIFT  49
#define TILE    54
#define PATCH   60
#define NTOT_D  4572288.0

#define STATS_BLOCKS  1568          // 7*7*32
#define ROWS_TOTAL    (BATCH * H)   // 12288
#define ROW_BLOCKS    1756          // ceil(12288 / 7)
#define MAIN_BLOCKS   (STATS_BLOCKS + ROW_BLOCKS)
#define ZB            1184          // zcorr blocks (8 per SM)
#define ZGROUPS       (ZB * 4)      // 64-thread groups
#define ZW_BLOCKS     (ZB + 28)
#define MAE_BLOCKS    1512          // 12096 rows / 8 warps

// ---------------- global scratch (no allocations allowed) ----------------
__device__ double g_tp[NSHIFT];            // dense cross: sum t*p per shift
__device__ double g_zp[NSHIFT];            // sparse cross: sum z*p per shift
__device__ double g_win[NSHIFT * 4];       // windowed sums: t, t^2, m, m*t
__device__ double g_sp[32];                // global sum p (spread slots)
__device__ double g_sp2[32];               // global sum p^2 (spread slots)
__device__ double g_abs[32];               // MAE accumulation (spread slots)
__device__ int    g_idx;
__device__ unsigned int g_zcount;
__device__ unsigned int g_done_zw;
__device__ unsigned int g_done_mae;
__device__ float  g_W[4 * NS * BATCH * H]; // per-row windowed sums [f][v][b][y]
__device__ int    g_zlist[BATCH * H * H];  // worst-case capacity

__global__ void init_kernel() {
    int t = threadIdx.x;
    if (t < NSHIFT) { g_tp[t] = 0.0; g_zp[t] = 0.0; }
    if (t < 32) { g_sp[t] = 0.0; g_sp2[t] = 0.0; g_abs[t] = 0.0; }
    if (t == 0) { g_idx = 0; g_zcount = 0u; g_done_zw = 0u; g_done_mae = 0u; }
}

// ======== fused main kernel: stats blocks + rowsum blocks ========
__global__ __launch_bounds__(224) void main_kernel(
    const float* __restrict__ pred, const float* __restrict__ target)
{
    __shared__ float sT[PATCH * PATCH];
    __shared__ float sP[TILE * TILE];

    const int tid  = threadIdx.x;
    const int lane = tid & 31;
    const int wid  = tid >> 5;

    if (blockIdx.x < STATS_BLOCKS) {
        // ---- dense cross-correlation: sum t*p per shift (1 FFMA / pair) ----
        const int bid = blockIdx.x;
        const int tx = bid % 7;
        const int ty = (bid / 7) % 7;
        const int b  = bid / 49;
        const int x0 = tx * TILE;
        const int y0 = ty * TILE;
        const float* tb = target + (size_t)b * H * H;
        const float* pb = pred   + (size_t)b * H * H;

        for (int k = tid; k < PATCH * PATCH; k += 224) {
            int yy = k / PATCH, xx = k - yy * PATCH;
            sT[k] = tb[(y0 + yy) * H + (x0 + xx)];
        }
        for (int k = tid; k < TILE * TILE; k += 224) {
            int i = k / TILE, j = k - i * TILE;
            sP[k] = pb[(y0 + i + 3) * H + (x0 + j + 3)];
        }
        __syncthreads();

        float acc[NS];
#pragma unroll
        for (int v = 0; v < NS; v++) acc[v] = 0.f;

        // 54 rows x 9 groups of 6 px; t-row register reuse (12 t / 42 FMA)
        for (int g = lane; g < 486; g += 32) {
            int i = g / 9;
            int j = (g - i * 9) * 6;
            const float2* trow = reinterpret_cast<const float2*>(&sT[(i + wid) * PATCH + j]);
            const float2* prow = reinterpret_cast<const float2*>(&sP[i * TILE + j]);
            float tt[12], pp[6];
#pragma unroll
            for (int k = 0; k < 6; k++) { float2 q = trow[k]; tt[2*k] = q.x; tt[2*k+1] = q.y; }
#pragma unroll
            for (int k = 0; k < 3; k++) { float2 q = prow[k]; pp[2*k] = q.x; pp[2*k+1] = q.y; }
#pragma unroll
            for (int px = 0; px < 6; px++) {
                float p = pp[px];
#pragma unroll
                for (int v = 0; v < NS; v++)
                    acc[v] = fmaf(tt[px + v], p, acc[v]);
            }
        }

#pragma unroll
        for (int v = 0; v < NS; v++) {
            float tp = acc[v];
            for (int o = 16; o; o >>= 1)
                tp += __shfl_xor_sync(0xffffffffu, tp, o);
            if (lane == 0)
                atomicAdd(&g_tp[wid * NS + v], (double)tp);
        }
    } else {
        // ---- per-row windowed sums + pred sums + z compaction ----
        const int gw = (blockIdx.x - STATS_BLOCKS) * 7 + wid;
        if (gw >= ROWS_TOTAL) return;
        const int b = gw / H;
        const int y = gw - b * H;
        const float* row = target + ((size_t)b * H + y) * H;

        float s0 = 0.f, s1 = 0.f, s2 = 0.f, s3 = 0.f;
        unsigned zm = 0u;
#pragma unroll
        for (int k = 0; k < 12; k++) {
            int x = lane + 32 * k;
            float t = row[x];
            float m = (t > 5.f) ? 1.f : 0.f;
            s0 += t;
            s1  = fmaf(t, t, s1);
            s2 += m;
            s3  = fmaf(m, t, s3);
            if (t <= 5.f) zm |= (1u << k);
        }

        // compact z pixels: one atomic per row
        {
            unsigned cnt = (unsigned)__popc(zm);
            unsigned pre = cnt;
            for (int o = 1; o < 32; o <<= 1) {
                unsigned n = __shfl_up_sync(0xffffffffu, pre, o);
                if (lane >= o) pre += n;
            }
            unsigned tot  = __shfl_sync(0xffffffffu, pre, 31);
            unsigned excl = pre - cnt;
            unsigned base = 0;
            if (tot) {
                if (lane == 31) base = atomicAdd(&g_zcount, tot);
                base = __shfl_sync(0xffffffffu, base, 31);
                unsigned idx = base + excl;
                unsigned mm = zm;
                while (mm) {
                    int k = __ffs(mm) - 1;
                    mm &= mm - 1;
                    g_zlist[idx++] = (b * H + y) * H + lane + 32 * k;
                }
            }
        }

        for (int o = 16; o; o >>= 1) {
            s0 += __shfl_xor_sync(0xffffffffu, s0, o);
            s1 += __shfl_xor_sync(0xffffffffu, s1, o);
            s2 += __shfl_xor_sync(0xffffffffu, s2, o);
            s3 += __shfl_xor_sync(0xffffffffu, s3, o);
        }

        if (lane == 0) {
            float e[12];
#pragma unroll
            for (int k = 0; k < 6; k++) { e[k] = row[k]; e[6 + k] = row[378 + k]; }
#pragma unroll
            for (int v = 0; v < NS; v++) {
                float L0 = 0.f, L1 = 0.f, L2 = 0.f, L3 = 0.f;
                for (int x = 0; x < v; x++) {
                    float t = e[x];
                    float m = (t > 5.f) ? 1.f : 0.f;
                    L0 += t; L1 += t * t; L2 += m; L3 += m * t;
                }
                float R0 = 0.f, R1 = 0.f, R2 = 0.f, R3 = 0.f;
                for (int k = v; k < 6; k++) {
                    float t = e[6 + k];
                    float m = (t > 5.f) ? 1.f : 0.f;
                    R0 += t; R1 += t * t; R2 += m; R3 += m * t;
                }
                g_W[((0 * NS + v) * BATCH + b) * H + y] = s0 - L0 - R0;
                g_W[((1 * NS + v) * BATCH + b) * H + y] = s1 - L1 - R1;
                g_W[((2 * NS + v) * BATCH + b) * H + y] = s2 - L2 - R2;
                g_W[((3 * NS + v) * BATCH + b) * H + y] = s3 - L3 - R3;
            }
        }

        if (y >= 3 && y < 381) {
            const float* prow = pred + ((size_t)b * H + y) * H;
            float sp = 0.f, sp2 = 0.f;
#pragma unroll
            for (int k = 0; k < 12; k++) {
                int x = 3 + lane + 32 * k;
                if (x < 381) {
                    float p = prow[x];
                    sp += p;
                    sp2 = fmaf(p, p, sp2);
                }
            }
            for (int o = 16; o; o >>= 1) {
                sp  += __shfl_xor_sync(0xffffffffu, sp,  o);
                sp2 += __shfl_xor_sync(0xffffffffu, sp2, o);
            }
            if (lane == 0) {
                atomicAdd(&g_sp [gw & 31], (double)sp);
                atomicAdd(&g_sp2[gw & 31], (double)sp2);
            }
        }
    }
}

// ======== fused: zcorr blocks + winsum blocks + last-block argmin ========
__global__ __launch_bounds__(256) void zw_kernel(const float* __restrict__ pred,
                                                 float* out)
{
    __shared__ float  sAcc[64];
    __shared__ double col[H];
    __shared__ double red[256];
    __shared__ double scmse[64];
    __shared__ int    sidx[64];
    __shared__ int    sLast;

    const int tid = threadIdx.x;

    if (blockIdx.x < ZB) {
        // ---- sparse correction: shift-per-thread, 2-deep pipelined loads ----
        if (tid < 64) sAcc[tid] = 0.f;
        __syncthreads();

        const int sid = tid & 63;                 // shift id (only < 49 active)
        const int u = sid / NS, v = sid - (sid / NS) * NS;
        const bool active = sid < NSHIFT;
        const int grp = (blockIdx.x * 256 + tid) >> 6;  // 64-thread group id
        const int count = (int)g_zcount;

        float acc = 0.f;
        int zi = grp;
        for (; zi + ZGROUPS < count; zi += 2 * ZGROUPS) {
            // two independent code loads up front
            int code0 = g_zlist[zi];
            int code1 = g_zlist[zi + ZGROUPS];
            int b0 = code0 / (H * H), r0 = code0 - b0 * (H * H);
            int y0 = r0 / H,          x0 = r0 - y0 * H;
            int b1 = code1 / (H * H), r1 = code1 - b1 * (H * H);
            int y1 = r1 / H,          x1 = r1 - y1 * H;
            if (active) {
                int yy0 = y0 - u, xx0 = x0 - v;
                int yy1 = y1 - u, xx1 = x1 - v;
                bool ok0 = (yy0 >= 0 && yy0 < KK && xx0 >= 0 && xx0 < KK);
                bool ok1 = (yy1 >= 0 && yy1 < KK && xx1 >= 0 && xx1 < KK);
                float p0 = ok0 ? pred[(size_t)b0 * H * H + (yy0 + 3) * H + (xx0 + 3)] : 0.f;
                float p1 = ok1 ? pred[(size_t)b1 * H * H + (yy1 + 3) * H + (xx1 + 3)] : 0.f;
                acc += p0 + p1;
            }
        }
        for (; zi < count; zi += ZGROUPS) {
            int code = g_zlist[zi];
            int b = code / (H * H);
            int r = code - b * (H * H);
            int y = r / H;
            int x = r - y * H;
            if (active) {
                int yy = y - u, xx = x - v;
                if (yy >= 0 && yy < KK && xx >= 0 && xx < KK)
                    acc += pred[(size_t)b * H * H + (yy + 3) * H + (xx + 3)];
            }
        }
        if (active && acc != 0.f) atomicAdd(&sAcc[sid], acc);
        __syncthreads();
        if (tid < NSHIFT && sAcc[tid] != 0.f)
            atomicAdd(&g_zp[tid], (double)sAcc[tid]);
    } else {
        // ---- combine per-row windowed sums: block per (f, v) ----
        const int wb = blockIdx.x - ZB;
        const int f = wb / NS;
        const int v = wb - f * NS;
        const float* Wfv = &g_W[((f * NS + v) * BATCH) * H];

        for (int y = tid; y < H; y += 256) {
            double s = 0.0;
#pragma unroll 4
            for (int b = 0; b < BATCH; b++)
                s += (double)Wfv[b * H + y];
            col[y] = s;
        }
        __syncthreads();

        double s = col[tid];
        if (tid + 256 < H) s += col[tid + 256];
        red[tid] = s;
        __syncthreads();
        for (int o = 128; o; o >>= 1) {
            if (tid < o) red[tid] += red[tid + o];
            __syncthreads();
        }
        if (tid < NS) {
            double T = red[0];
            for (int y = 0; y < tid; y++) T -= col[y];
            for (int y = tid + KK; y < H; y++) T -= col[y];
            g_win[(tid * NS + v) * 4 + f] = T;
        }
    }

    // ---- last block performs argmin + cPSNR ----
    __threadfence();
    __syncthreads();
    if (tid == 0)
        sLast = (atomicAdd(&g_done_zw, 1u) == (unsigned)(gridDim.x - 1));
    __syncthreads();
    if (!sLast) return;

    volatile double* vtp  = g_tp;
    volatile double* vzp  = g_zp;
    volatile double* vwin = g_win;
    volatile double* vsp  = g_sp;
    volatile double* vsp2 = g_sp2;

    double Sp = 0.0, Sp2 = 0.0;
    for (int k = 0; k < 32; k++) { Sp += vsp[k]; Sp2 += vsp2[k]; }

    if (tid < 64) {
        double c = 1e300;
        if (tid < NSHIFT) {
            double wt  = vwin[tid * 4 + 0];
            double wt2 = vwin[tid * 4 + 1];
            double n   = vwin[tid * 4 + 2];
            double wmt = vwin[tid * 4 + 3];
            double Sd  = wt - Sp;
            double Sd2 = wt2 - 2.0 * vtp[tid] + Sp2;
            double Sm  = wmt - (Sp - vzp[tid]);   // sum m*p = Sp - sum z*p
            double bb  = Sm / n;
            c = (Sd2 - 2.0 * bb * Sd + NTOT_D * bb * bb) / n;
        }
        scmse[tid] = c; sidx[tid] = tid;
    }
    __syncthreads();
    for (int o = 32; o; o >>= 1) {
        if (tid < o) {
            if (scmse[tid + o] < scmse[tid]) {
                scmse[tid] = scmse[tid + o];
                sidx[tid]  = sidx[tid + o];
            }
        }
        __syncthreads();
    }
    if (tid == 0) {
        g_idx  = sidx[0];
        out[0] = (float)(-10.0 * log10(scmse[0]));
    }
}

// ======== MAE over winning shift + last-block finalize ========
__global__ __launch_bounds__(256) void mae_kernel(
    const float* __restrict__ pred, const float* __restrict__ target, float* out)
{
    const int idx = g_idx;
    const int u = idx / NS, v = idx - (idx / NS) * NS;
    const int gw   = blockIdx.x * 8 + (threadIdx.x >> 5);   // 0 .. 12095
    const int lane = threadIdx.x & 31;
    const int b    = gw / KK;
    const int i    = gw - b * KK;

    const float* prow = pred   + ((size_t)b * H + i + 3) * H + 3;
    const float* trow = target + ((size_t)b * H + i + u) * H + v;

    // fully unrolled: 378 = 32*11 + 26; two accumulators for ILP
    float a0 = 0.f, a1 = 0.f;
#pragma unroll
    for (int k = 0; k < 11; k++) {
        int x = lane + 32 * k;
        float d = fabsf(trow[x] - prow[x]);
        if (k & 1) a1 += d; else a0 += d;
    }
    if (lane < 26) {
        int x = lane + 352;
        a1 += fabsf(trow[x] - prow[x]);
    }
    float acc = a0 + a1;
    for (int o = 16; o; o >>= 1) acc += __shfl_xor_sync(0xffffffffu, acc, o);

    __shared__ float ssum[8];
    __shared__ int   sLast;
    const int w = threadIdx.x >> 5;
    if (lane == 0) ssum[w] = acc;
    __syncthreads();
    if (threadIdx.x == 0) {
        float a = 0.f;
#pragma unroll
        for (int k = 0; k < 8; k++) a += ssum[k];
        atomicAdd(&g_abs[blockIdx.x & 31], (double)a);
        __threadfence();
        sLast = (atomicAdd(&g_done_mae, 1u) == (unsigned)(gridDim.x - 1));
        if (sLast) {
            volatile double* ga = g_abs;
            double s = 0.0;
            for (int k = 0; k < 32; k++) s += ga[k];
            out[1] = (float)(s / NTOT_D);
        }
    }
}

extern "C" void kernel_launch(void* const* d_in, const int* in_sizes, int n_in,
                              void* d_out, int out_size) {
    const float* pred   = (const float*)d_in[0];
    const float* target = (const float*)d_in[1];
    float* out = (float*)d_out;

    init_kernel<<<1, 64>>>();
    main_kernel<<<MAIN_BLOCKS, 224>>>(pred, target);
    zw_kernel<<<ZW_BLOCKS, 256>>>(pred, out);
    mae_kernel<<<MAE_BLOCKS, 256>>>(pred, target, out);
}

// round 8
// speedup vs baseline: 1.1016x; 1.0418x over previous
#include <cuda_runtime.h>
#include <math.h>

#define BATCH   32
#define H       384
#define KK      378
#define NS      7
#define NSHIFT  49
#define TILE    54
#define PATCH   60
#define NTOT_D  4572288.0

#define STATS_BLOCKS  1568          // 7*7*32
#define ROWS_TOTAL    (BATCH * H)   // 12288
#define ROW_BLOCKS    1756          // ceil(12288 / 7)
#define MAIN_BLOCKS   (STATS_BLOCKS + ROW_BLOCKS)
#define ZB            1184          // zcorr blocks
#define ZGROUPS       (ZB * 4)      // 64-thread groups
#define ZW_BLOCKS     (ZB + 28)
#define MAE_BLOCKS    1512          // 12096 rows / 8 warps

// ---------------- global scratch (no allocations allowed) ----------------
__device__ double g_tp[NSHIFT];            // dense cross: sum t*p per shift
__device__ double g_zp[NSHIFT];            // sparse cross: sum z*p per shift
__device__ double g_win[NSHIFT * 4];       // windowed sums: t, t^2, m, m*t
__device__ double g_sp[32];                // global sum p (spread slots)
__device__ double g_sp2[32];               // global sum p^2 (spread slots)
__device__ double g_abs[32];               // MAE accumulation (spread slots)
__device__ int    g_idx;
__device__ unsigned int g_zcount;
__device__ unsigned int g_done_zw;
__device__ unsigned int g_done_mae;
__device__ float  g_W[4 * NS * BATCH * H]; // per-row windowed sums [f][v][b][y]
__device__ int    g_zlist[BATCH * H * H];  // worst-case capacity

__global__ void init_kernel() {
    int t = threadIdx.x;
    if (t < NSHIFT) { g_tp[t] = 0.0; g_zp[t] = 0.0; }
    if (t < 32) { g_sp[t] = 0.0; g_sp2[t] = 0.0; g_abs[t] = 0.0; }
    if (t == 0) { g_idx = 0; g_zcount = 0u; g_done_zw = 0u; g_done_mae = 0u; }
}

// ======== fused main kernel: stats blocks + rowsum blocks ========
__global__ __launch_bounds__(224) void main_kernel(
    const float* __restrict__ pred, const float* __restrict__ target)
{
    __shared__ float sT[PATCH * PATCH];
    __shared__ float sP[TILE * TILE];

    const int tid  = threadIdx.x;
    const int lane = tid & 31;
    const int wid  = tid >> 5;

    if (blockIdx.x < STATS_BLOCKS) {
        // ---- dense cross-correlation: warp = v shift, lane = column,
        //      sliding 7-row t window in registers. Conflict-free LDS. ----
        const int bid = blockIdx.x;
        const int tx = bid % 7;
        const int ty = (bid / 7) % 7;
        const int b  = bid / 49;
        const int x0 = tx * TILE;
        const int y0 = ty * TILE;
        const float* tb = target + (size_t)b * H * H;
        const float* pb = pred   + (size_t)b * H * H;

        for (int k = tid; k < PATCH * PATCH; k += 224) {
            int yy = k / PATCH, xx = k - yy * PATCH;
            sT[k] = tb[(y0 + yy) * H + (x0 + xx)];
        }
        for (int k = tid; k < TILE * TILE; k += 224) {
            int i = k / TILE, j = k - i * TILE;
            sP[k] = pb[(y0 + i + 3) * H + (x0 + j + 3)];
        }
        __syncthreads();

        const int v = wid;                     // this warp's v shift
        const bool two = (lane < TILE - 32);   // lanes 0..21 own 2nd column
        const int c0 = lane;                   // output column 1
        const int c1 = two ? lane + 32 : 0;    // output column 2 (clamped)

        const float* tcol0 = &sT[c0 + v];
        const float* tcol1 = &sT[c1 + v];
        const float* pcol0 = &sP[c0];
        const float* pcol1 = &sP[c1];

        float acc[NS];
#pragma unroll
        for (int u = 0; u < NS; u++) acc[u] = 0.f;

        float ta[NS], tbv[NS];
#pragma unroll
        for (int k = 0; k < 6; k++) {
            ta[k]  = tcol0[k * PATCH];
            tbv[k] = tcol1[k * PATCH];
        }

#pragma unroll 6
        for (int i = 0; i < TILE; i++) {
            ta[6]  = tcol0[(i + 6) * PATCH];
            tbv[6] = tcol1[(i + 6) * PATCH];
            float p0 = pcol0[i * TILE];
            float p1 = two ? pcol1[i * TILE] : 0.f;
#pragma unroll
            for (int u = 0; u < NS; u++) {
                acc[u] = fmaf(ta[u],  p0, acc[u]);
                acc[u] = fmaf(tbv[u], p1, acc[u]);
            }
#pragma unroll
            for (int k = 0; k < 6; k++) { ta[k] = ta[k + 1]; tbv[k] = tbv[k + 1]; }
        }

#pragma unroll
        for (int u = 0; u < NS; u++) {
            float tp = acc[u];
            for (int o = 16; o; o >>= 1)
                tp += __shfl_xor_sync(0xffffffffu, tp, o);
            if (lane == 0)
                atomicAdd(&g_tp[u * NS + v], (double)tp);
        }
    } else {
        // ---- per-row windowed sums + pred sums + z compaction ----
        const int gw = (blockIdx.x - STATS_BLOCKS) * 7 + wid;
        if (gw >= ROWS_TOTAL) return;
        const int b = gw / H;
        const int y = gw - b * H;
        const float* row = target + ((size_t)b * H + y) * H;

        float s0 = 0.f, s1 = 0.f, s2 = 0.f, s3 = 0.f;
        unsigned zm = 0u;
#pragma unroll
        for (int k = 0; k < 12; k++) {
            int x = lane + 32 * k;
            float t = row[x];
            float m = (t > 5.f) ? 1.f : 0.f;
            s0 += t;
            s1  = fmaf(t, t, s1);
            s2 += m;
            s3  = fmaf(m, t, s3);
            if (t <= 5.f) zm |= (1u << k);
        }

        // compact z pixels: one atomic per row
        {
            unsigned cnt = (unsigned)__popc(zm);
            unsigned pre = cnt;
            for (int o = 1; o < 32; o <<= 1) {
                unsigned n = __shfl_up_sync(0xffffffffu, pre, o);
                if (lane >= o) pre += n;
            }
            unsigned tot  = __shfl_sync(0xffffffffu, pre, 31);
            unsigned excl = pre - cnt;
            unsigned base = 0;
            if (tot) {
                if (lane == 31) base = atomicAdd(&g_zcount, tot);
                base = __shfl_sync(0xffffffffu, base, 31);
                unsigned idx = base + excl;
                unsigned mm = zm;
                while (mm) {
                    int k = __ffs(mm) - 1;
                    mm &= mm - 1;
                    g_zlist[idx++] = (b * H + y) * H + lane + 32 * k;
                }
            }
        }

        for (int o = 16; o; o >>= 1) {
            s0 += __shfl_xor_sync(0xffffffffu, s0, o);
            s1 += __shfl_xor_sync(0xffffffffu, s1, o);
            s2 += __shfl_xor_sync(0xffffffffu, s2, o);
            s3 += __shfl_xor_sync(0xffffffffu, s3, o);
        }

        if (lane == 0) {
            float e[12];
#pragma unroll
            for (int k = 0; k < 6; k++) { e[k] = row[k]; e[6 + k] = row[378 + k]; }
#pragma unroll
            for (int v = 0; v < NS; v++) {
                float L0 = 0.f, L1 = 0.f, L2 = 0.f, L3 = 0.f;
                for (int x = 0; x < v; x++) {
                    float t = e[x];
                    float m = (t > 5.f) ? 1.f : 0.f;
                    L0 += t; L1 += t * t; L2 += m; L3 += m * t;
                }
                float R0 = 0.f, R1 = 0.f, R2 = 0.f, R3 = 0.f;
                for (int k = v; k < 6; k++) {
                    float t = e[6 + k];
                    float m = (t > 5.f) ? 1.f : 0.f;
                    R0 += t; R1 += t * t; R2 += m; R3 += m * t;
                }
                g_W[((0 * NS + v) * BATCH + b) * H + y] = s0 - L0 - R0;
                g_W[((1 * NS + v) * BATCH + b) * H + y] = s1 - L1 - R1;
                g_W[((2 * NS + v) * BATCH + b) * H + y] = s2 - L2 - R2;
                g_W[((3 * NS + v) * BATCH + b) * H + y] = s3 - L3 - R3;
            }
        }

        if (y >= 3 && y < 381) {
            const float* prow = pred + ((size_t)b * H + y) * H;
            float sp = 0.f, sp2 = 0.f;
#pragma unroll
            for (int k = 0; k < 12; k++) {
                int x = 3 + lane + 32 * k;
                if (x < 381) {
                    float p = prow[x];
                    sp += p;
                    sp2 = fmaf(p, p, sp2);
                }
            }
            for (int o = 16; o; o >>= 1) {
                sp  += __shfl_xor_sync(0xffffffffu, sp,  o);
                sp2 += __shfl_xor_sync(0xffffffffu, sp2, o);
            }
            if (lane == 0) {
                atomicAdd(&g_sp [gw & 31], (double)sp);
                atomicAdd(&g_sp2[gw & 31], (double)sp2);
            }
        }
    }
}

// ======== fused: zcorr blocks + winsum blocks + last-block argmin ========
__global__ __launch_bounds__(256) void zw_kernel(const float* __restrict__ pred,
                                                 float* out)
{
    __shared__ float  sAcc[64];
    __shared__ double col[H];
    __shared__ double red[256];
    __shared__ double scmse[64];
    __shared__ int    sidx[64];
    __shared__ int    sLast;

    const int tid = threadIdx.x;

    if (blockIdx.x < ZB) {
        // ---- sparse correction: shift-per-thread, 2-deep pipelined loads ----
        if (tid < 64) sAcc[tid] = 0.f;
        __syncthreads();

        const int sid = tid & 63;
        const int u = sid / NS, v = sid - (sid / NS) * NS;
        const bool active = sid < NSHIFT;
        const int grp = (blockIdx.x * 256 + tid) >> 6;
        const int count = (int)g_zcount;

        float acc = 0.f;
        int zi = grp;
        for (; zi + ZGROUPS < count; zi += 2 * ZGROUPS) {
            int code0 = g_zlist[zi];
            int code1 = g_zlist[zi + ZGROUPS];
            int b0 = code0 / (H * H), r0 = code0 - b0 * (H * H);
            int y0 = r0 / H,          x0 = r0 - y0 * H;
            int b1 = code1 / (H * H), r1 = code1 - b1 * (H * H);
            int y1 = r1 / H,          x1 = r1 - y1 * H;
            if (active) {
                int yy0 = y0 - u, xx0 = x0 - v;
                int yy1 = y1 - u, xx1 = x1 - v;
                bool ok0 = (yy0 >= 0 && yy0 < KK && xx0 >= 0 && xx0 < KK);
                bool ok1 = (yy1 >= 0 && yy1 < KK && xx1 >= 0 && xx1 < KK);
                float p0 = ok0 ? pred[(size_t)b0 * H * H + (yy0 + 3) * H + (xx0 + 3)] : 0.f;
                float p1 = ok1 ? pred[(size_t)b1 * H * H + (yy1 + 3) * H + (xx1 + 3)] : 0.f;
                acc += p0 + p1;
            }
        }
        for (; zi < count; zi += ZGROUPS) {
            int code = g_zlist[zi];
            int b = code / (H * H);
            int r = code - b * (H * H);
            int y = r / H;
            int x = r - y * H;
            if (active) {
                int yy = y - u, xx = x - v;
                if (yy >= 0 && yy < KK && xx >= 0 && xx < KK)
                    acc += pred[(size_t)b * H * H + (yy + 3) * H + (xx + 3)];
            }
        }
        if (active && acc != 0.f) atomicAdd(&sAcc[sid], acc);
        __syncthreads();
        if (tid < NSHIFT && sAcc[tid] != 0.f)
            atomicAdd(&g_zp[tid], (double)sAcc[tid]);
    } else {
        // ---- combine per-row windowed sums: block per (f, v) ----
        const int wb = blockIdx.x - ZB;
        const int f = wb / NS;
        const int v = wb - f * NS;
        const float* Wfv = &g_W[((f * NS + v) * BATCH) * H];

        for (int y = tid; y < H; y += 256) {
            double s = 0.0;
#pragma unroll 4
            for (int b = 0; b < BATCH; b++)
                s += (double)Wfv[b * H + y];
            col[y] = s;
        }
        __syncthreads();

        double s = col[tid];
        if (tid + 256 < H) s += col[tid + 256];
        red[tid] = s;
        __syncthreads();
        for (int o = 128; o; o >>= 1) {
            if (tid < o) red[tid] += red[tid + o];
            __syncthreads();
        }
        if (tid < NS) {
            double T = red[0];
            for (int y = 0; y < tid; y++) T -= col[y];
            for (int y = tid + KK; y < H; y++) T -= col[y];
            g_win[(tid * NS + v) * 4 + f] = T;
        }
    }

    // ---- last block performs argmin + cPSNR ----
    __threadfence();
    __syncthreads();
    if (tid == 0)
        sLast = (atomicAdd(&g_done_zw, 1u) == (unsigned)(gridDim.x - 1));
    __syncthreads();
    if (!sLast) return;

    volatile double* vtp  = g_tp;
    volatile double* vzp  = g_zp;
    volatile double* vwin = g_win;
    volatile double* vsp  = g_sp;
    volatile double* vsp2 = g_sp2;

    double Sp = 0.0, Sp2 = 0.0;
    for (int k = 0; k < 32; k++) { Sp += vsp[k]; Sp2 += vsp2[k]; }

    if (tid < 64) {
        double c = 1e300;
        if (tid < NSHIFT) {
            double wt  = vwin[tid * 4 + 0];
            double wt2 = vwin[tid * 4 + 1];
            double n   = vwin[tid * 4 + 2];
            double wmt = vwin[tid * 4 + 3];
            double Sd  = wt - Sp;
            double Sd2 = wt2 - 2.0 * vtp[tid] + Sp2;
            double Sm  = wmt - (Sp - vzp[tid]);
            double bb  = Sm / n;
            c = (Sd2 - 2.0 * bb * Sd + NTOT_D * bb * bb) / n;
        }
        scmse[tid] = c; sidx[tid] = tid;
    }
    __syncthreads();
    for (int o = 32; o; o >>= 1) {
        if (tid < o) {
            if (scmse[tid + o] < scmse[tid]) {
                scmse[tid] = scmse[tid + o];
                sidx[tid]  = sidx[tid + o];
            }
        }
        __syncthreads();
    }
    if (tid == 0) {
        g_idx  = sidx[0];
        out[0] = (float)(-10.0 * log10(scmse[0]));
    }
}

// ======== MAE over winning shift + last-block finalize ========
__global__ __launch_bounds__(256) void mae_kernel(
    const float* __restrict__ pred, const float* __restrict__ target, float* out)
{
    const int idx = g_idx;
    const int u = idx / NS, v = idx - (idx / NS) * NS;
    const int gw   = blockIdx.x * 8 + (threadIdx.x >> 5);   // 0 .. 12095
    const int lane = threadIdx.x & 31;
    const int b    = gw / KK;
    const int i    = gw - b * KK;

    const float* prow = pred   + ((size_t)b * H + i + 3) * H + 3;
    const float* trow = target + ((size_t)b * H + i + u) * H + v;

    // fully unrolled: 378 = 32*11 + 26; two accumulators for ILP
    float a0 = 0.f, a1 = 0.f;
#pragma unroll
    for (int k = 0; k < 11; k++) {
        int x = lane + 32 * k;
        float d = fabsf(trow[x] - prow[x]);
        if (k & 1) a1 += d; else a0 += d;
    }
    if (lane < 26) {
        int x = lane + 352;
        a1 += fabsf(trow[x] - prow[x]);
    }
    float acc = a0 + a1;
    for (int o = 16; o; o >>= 1) acc += __shfl_xor_sync(0xffffffffu, acc, o);

    __shared__ float ssum[8];
    __shared__ int   sLast;
    const int w = threadIdx.x >> 5;
    if (lane == 0) ssum[w] = acc;
    __syncthreads();
    if (threadIdx.x == 0) {
        float a = 0.f;
#pragma unroll
        for (int k = 0; k < 8; k++) a += ssum[k];
        atomicAdd(&g_abs[blockIdx.x & 31], (double)a);
        __threadfence();
        sLast = (atomicAdd(&g_done_mae, 1u) == (unsigned)(gridDim.x - 1));
        if (sLast) {
            volatile double* ga = g_abs;
            double s = 0.0;
            for (int k = 0; k < 32; k++) s += ga[k];
            out[1] = (float)(s / NTOT_D);
        }
    }
}

extern "C" void kernel_launch(void* const* d_in, const int* in_sizes, int n_in,
                              void* d_out, int out_size) {
    const float* pred   = (const float*)d_in[0];
    const float* target = (const float*)d_in[1];
    float* out = (float*)d_out;

    init_kernel<<<1, 64>>>();
    main_kernel<<<MAIN_BLOCKS, 224>>>(pred, target);
    zw_kernel<<<ZW_BLOCKS, 256>>>(pred, out);
    mae_kernel<<<MAE_BLOCKS, 256>>>(pred, target, out);
}